// round 15
// baseline (speedup 1.0000x reference)
#include <cuda_runtime.h>
#include <cuda_bf16.h>
#include <cstdint>

#define BSZ 2
#define LSEQ 1024
#define DM 768
#define DI 1536
#define DS 16
#define DC 4
#define DTR 48
#define NL 24
#define RWS (BSZ*LSEQ)
#define DBLW (DTR + 2*DS)       /* 80 */
#define EPSF 1e-5f
#define XP_SLICES 8
#define XP_KLEN (DI/XP_SLICES)  /* 192 */

typedef __nv_bfloat16 bf16;
typedef __nv_bfloat162 bf162;

// ---------------------------------------------------------------------------
// Scratch
// ---------------------------------------------------------------------------
__device__ float g_x[2][RWS*DM];
__device__ float g_xz[2][RWS*2*DI];
__device__ float g_xc[2][RWS*DI];
__device__ float g_delta[2][RWS*DI];
__device__ float g_xp_part[2][XP_SLICES][RWS*128];

__device__ bf16 g_h_hi[2][RWS*DM],   g_h_lo[2][RWS*DM];
__device__ bf16 g_y_hi[2][RWS*DI],   g_y_lo[2][RWS*DI];

__device__ bf16 g_wip_hi[2][NL*2*DI*DM], g_wip_lo[2][NL*2*DI*DM];
__device__ bf16 g_wxp_hi[2][NL*DBLW*DI], g_wxp_lo[2][NL*DBLW*DI];
__device__ bf16 g_wdt_hi[2][NL*DI*DTR],  g_wdt_lo[2][NL*DI*DTR];
__device__ bf16 g_wop_hi[2][NL*DM*DI],   g_wop_lo[2][NL*DM*DI];

__device__ __forceinline__ uint32_t smem_u32(const void* p) {
    uint32_t a;
    asm("{ .reg .u64 t; cvta.to.shared.u64 t, %1; cvt.u32.u64 %0, t; }" : "=r"(a) : "l"(p));
    return a;
}

__device__ __forceinline__ void fsplit(float v, bf16* hp, bf16* lp) {
    bf16 h = __float2bfloat16_rn(v);
    *hp = h;
    *lp = __float2bfloat16_rn(v - __bfloat162float(h));
}

__device__ __forceinline__ uint32_t pk2(bf16 a, bf16 b) {
    bf162 t; t.x = a; t.y = b;
    return *(uint32_t*)&t;
}

#define CP16(dst, src, sz) \
    asm volatile("cp.async.cg.shared.global [%0], [%1], 16, %2;" \
        :: "r"(dst), "l"(src), "r"(sz) : "memory")
#define CP_COMMIT() asm volatile("cp.async.commit_group;" ::: "memory")
#define CP_WAIT1()  asm volatile("cp.async.wait_group 1;" ::: "memory")
#define CP_WAIT0()  asm volatile("cp.async.wait_group 0;" ::: "memory")

#define LDSM4(r, addr) \
    asm volatile("ldmatrix.sync.aligned.m8n8.x4.shared.b16 {%0,%1,%2,%3}, [%4];" \
        : "=r"((r)[0]), "=r"((r)[1]), "=r"((r)[2]), "=r"((r)[3]) : "r"(addr))

#define MMA16816(c, a, b0v, b1v) \
    asm volatile("mma.sync.aligned.m16n8k16.row.col.f32.bf16.bf16.f32 " \
        "{%0,%1,%2,%3}, {%4,%5,%6,%7}, {%8,%9}, {%0,%1,%2,%3};" \
        : "+f"((c)[0]), "+f"((c)[1]), "+f"((c)[2]), "+f"((c)[3]) \
        : "r"((a)[0]), "r"((a)[1]), "r"((a)[2]), "r"((a)[3]), "r"(b0v), "r"(b1v))

// ---------------------------------------------------------------------------
// Weight split kernels
// ---------------------------------------------------------------------------
__global__ void k_wsplit(const float4* __restrict__ sF, const float4* __restrict__ sB,
                         bf162* __restrict__ hF, bf162* __restrict__ lF,
                         bf162* __restrict__ hB, bf162* __restrict__ lB, int n4) {
    int i = blockIdx.x * blockDim.x + threadIdx.x;
    if (i >= n4) return;
    const float4* src = blockIdx.y ? sB : sF;
    bf162* hi = blockIdx.y ? hB : hF;
    bf162* lo = blockIdx.y ? lB : lF;
    float4 v = src[i];
    bf162 h01 = __floats2bfloat162_rn(v.x, v.y);
    bf162 h23 = __floats2bfloat162_rn(v.z, v.w);
    bf162 l01 = __floats2bfloat162_rn(v.x - __bfloat162float(h01.x),
                                      v.y - __bfloat162float(h01.y));
    bf162 l23 = __floats2bfloat162_rn(v.z - __bfloat162float(h23.x),
                                      v.w - __bfloat162float(h23.y));
    hi[i*2] = h01; hi[i*2+1] = h23;
    lo[i*2] = l01; lo[i*2+1] = l23;
}

__global__ void k_wsplit2(const float4* __restrict__ s0F, const float4* __restrict__ s0B,
                          bf162* __restrict__ h0F, bf162* __restrict__ l0F,
                          bf162* __restrict__ h0B, bf162* __restrict__ l0B, int n40,
                          const float4* __restrict__ s1F, const float4* __restrict__ s1B,
                          bf162* __restrict__ h1F, bf162* __restrict__ l1F,
                          bf162* __restrict__ h1B, bf162* __restrict__ l1B, int n41) {
    int i = blockIdx.x * blockDim.x + threadIdx.x;
    int set = blockIdx.y >> 1, dir = blockIdx.y & 1;
    const float4* src; bf162 *hi, *lo; int n4;
    if (set == 0) { src = dir ? s0B : s0F; hi = dir ? h0B : h0F; lo = dir ? l0B : l0F; n4 = n40; }
    else          { src = dir ? s1B : s1F; hi = dir ? h1B : h1F; lo = dir ? l1B : l1F; n4 = n41; }
    if (i >= n4) return;
    float4 v = src[i];
    bf162 h01 = __floats2bfloat162_rn(v.x, v.y);
    bf162 h23 = __floats2bfloat162_rn(v.z, v.w);
    bf162 l01 = __floats2bfloat162_rn(v.x - __bfloat162float(h01.x),
                                      v.y - __bfloat162float(h01.y));
    bf162 l23 = __floats2bfloat162_rn(v.z - __bfloat162float(h23.x),
                                      v.w - __bfloat162float(h23.y));
    hi[i*2] = h01; hi[i*2+1] = h23;
    lo[i*2] = l01; lo[i*2+1] = l23;
}

// ---------------------------------------------------------------------------
// Embedding
// ---------------------------------------------------------------------------
__global__ void k_embed(const int* __restrict__ ids,
                        const float* __restrict__ embF,
                        const float* __restrict__ embB) {
    int row = blockIdx.x, dir = blockIdx.y;
    int b = row / LSEQ, l = row % LSEQ;
    int tok = (dir == 0) ? ids[b*LSEQ + l] : ids[b*LSEQ + (LSEQ-1-l)];
    const float* emb = (dir == 0) ? embF : embB;
    const float4* src = (const float4*)(emb + (size_t)tok * DM);
    float4* dst = (float4*)(g_x[dir] + (size_t)row * DM);
    for (int i = threadIdx.x; i < DM/4; i += blockDim.x) dst[i] = src[i];
}

// ---------------------------------------------------------------------------
// RMSNorm -> bf16 hi/lo
// ---------------------------------------------------------------------------
__global__ void k_rmsnorm(const float* __restrict__ wF, const float* __restrict__ wB) {
    int row = blockIdx.x, dir = blockIdx.y;
    const float* x = g_x[dir] + (size_t)row * DM;
    bf16* hh = g_h_hi[dir] + (size_t)row * DM;
    bf16* hl = g_h_lo[dir] + (size_t)row * DM;
    const float* w = dir ? wB : wF;
    float s = 0.f;
    for (int i = threadIdx.x; i < DM; i += 256) { float v = x[i]; s += v*v; }
    #pragma unroll
    for (int o = 16; o; o >>= 1) s += __shfl_down_sync(0xffffffffu, s, o);
    __shared__ float red[8];
    if ((threadIdx.x & 31) == 0) red[threadIdx.x >> 5] = s;
    __syncthreads();
    if (threadIdx.x < 8) {
        float t = red[threadIdx.x];
        #pragma unroll
        for (int o = 4; o; o >>= 1) t += __shfl_down_sync(0xffu, t, o);
        if (threadIdx.x == 0) red[0] = t;
    }
    __syncthreads();
    float inv = rsqrtf(red[0] / (float)DM + EPSF);
    for (int i = threadIdx.x; i < DM; i += 256) {
        float v = x[i] * inv * w[i];
        fsplit(v, hh + i, hl + i);
    }
}

// ===========================================================================
// Shared GEMM fragment addressing helpers (SW128 within 128B rows)
// ===========================================================================
#define GTK 64

// ===========================================================================
// KERNEL B: 128x64 tile, 256 threads, 2 CTAs/SM (in_proj, out_proj)
// ===========================================================================
#define STAGE256 49152
#define SMEM256 (2*STAGE256)

__device__ __forceinline__ void stage256(
    uint32_t stg,
    const bf16* __restrict__ Ahi, const bf16* __restrict__ Alo,
    const bf16* __restrict__ Whi, const bf16* __restrict__ Wlo,
    int m0, int n0, int k0, int lda, int ldw, int N, int K, int tid)
{
    #pragma unroll
    for (int t = 0; t < 4; t++) {
        int idx = tid + t*256;
        int row = idx >> 3, col = idx & 7;
        int kk = k0 + col*8;
        uint32_t soff = (uint32_t)(row*128 + ((col*16) ^ ((row & 7) << 4)));
        int v = (kk < K) ? 16 : 0;
        size_t go = (size_t)(m0+row)*lda + (v ? kk : 0);
        CP16(stg + soff,         Ahi + go, v);
        CP16(stg + 16384 + soff, Alo + go, v);
    }
    #pragma unroll
    for (int t = 0; t < 2; t++) {
        int idx = tid + t*256;
        int row = idx >> 3, col = idx & 7;
        int kk = k0 + col*8;
        uint32_t soff = (uint32_t)(row*128 + ((col*16) ^ ((row & 7) << 4)));
        int gn = n0 + row;
        int v = (gn < N && kk < K) ? 16 : 0;
        size_t go = (size_t)(v ? gn : 0)*ldw + (v ? kk : 0);
        CP16(stg + 32768 + soff, Whi + go, v);
        CP16(stg + 40960 + soff, Wlo + go, v);
    }
}

__global__ __launch_bounds__(256, 2)
void k_gemm256(int aId, int lda,
               const bf16* __restrict__ Whi0, const bf16* __restrict__ Wlo0,
               const bf16* __restrict__ Whi1, const bf16* __restrict__ Wlo1,
               int cfId, float* __restrict__ outp, int M, int N, int K)
{
    extern __shared__ __align__(1024) char smem[];
    const int dir = blockIdx.z;
    const bf16* Ahi = (aId == 0) ? g_h_hi[dir] : g_y_hi[dir];
    const bf16* Alo = (aId == 0) ? g_h_lo[dir] : g_y_lo[dir];
    const bf16* Whi = dir ? Whi1 : Whi0;
    const bf16* Wlo = dir ? Wlo1 : Wlo0;

    const uint32_t tb = smem_u32(smem);
    const int tid = threadIdx.x, lane = tid & 31, wid = tid >> 5;
    const int wm = wid & 3, wn = wid >> 2;
    const int m0 = blockIdx.y * 128;
    const int n0 = blockIdx.x * 64;

    const int l15 = lane & 15;
    const int a_kbx = (lane & 16) ? 16 : 0;
    const int b_nrow = (lane & 7) + ((lane & 16) ? 8 : 0);
    const int b_kbx = (lane & 8) ? 16 : 0;

    uint32_t aOff[2], aMsk[2];
    #pragma unroll
    for (int mt = 0; mt < 2; mt++) {
        int r = wm*32 + mt*16 + l15;
        aOff[mt] = r * 128;
        aMsk[mt] = (r & 7) << 4;
    }
    uint32_t bOff[2], bMsk[2];
    #pragma unroll
    for (int g = 0; g < 2; g++) {
        int r = wn*32 + g*16 + b_nrow;
        bOff[g] = r * 128;
        bMsk[g] = (r & 7) << 4;
    }

    float cf[2][4][4];
    #pragma unroll
    for (int i = 0; i < 2; i++)
        #pragma unroll
        for (int j = 0; j < 4; j++)
            #pragma unroll
            for (int q = 0; q < 4; q++) cf[i][j][q] = 0.f;

    const int nch = (K + GTK - 1) / GTK;
    stage256(tb, Ahi, Alo, Whi, Wlo, m0, n0, 0, lda, K, N, K, tid);
    CP_COMMIT();

    for (int ch = 0; ch < nch; ch++) {
        if (ch + 1 < nch) {
            stage256(tb + ((ch+1)&1)*STAGE256, Ahi, Alo, Whi, Wlo,
                     m0, n0, (ch+1)*GTK, lda, K, N, K, tid);
            CP_COMMIT();
            CP_WAIT1();
        } else {
            CP_WAIT0();
        }
        __syncthreads();

        const uint32_t AHI = tb + (ch&1)*STAGE256;
        const uint32_t ALO = AHI + 16384, BHI = AHI + 32768, BLO = AHI + 40960;
        #pragma unroll
        for (int ks = 0; ks < 4; ks++) {
            const int kb = ks * 32;
            uint32_t ah[2][4], al[2][4], bh[2][4], bl[2][4];
            #pragma unroll
            for (int mt = 0; mt < 2; mt++) {
                uint32_t kx = (uint32_t)(kb + a_kbx) ^ aMsk[mt];
                LDSM4(ah[mt], AHI + aOff[mt] + kx);
                LDSM4(al[mt], ALO + aOff[mt] + kx);
            }
            #pragma unroll
            for (int g = 0; g < 2; g++) {
                uint32_t kx = (uint32_t)(kb + b_kbx) ^ bMsk[g];
                LDSM4(bh[g], BHI + bOff[g] + kx);
                LDSM4(bl[g], BLO + bOff[g] + kx);
            }
            #pragma unroll
            for (int mt = 0; mt < 2; mt++)
                #pragma unroll
                for (int nt = 0; nt < 4; nt++) {
                    int g = nt >> 1, o = (nt & 1) * 2;
                    float* cc = cf[mt][nt];
                    MMA16816(cc, ah[mt], bh[g][o], bh[g][o+1]);
                    MMA16816(cc, ah[mt], bl[g][o], bl[g][o+1]);
                    MMA16816(cc, al[mt], bh[g][o], bh[g][o+1]);
                }
        }
        __syncthreads();
    }

    float* Cf = (cfId == 1) ? g_xz[dir] : g_x[dir];
    const int mrow = m0 + wm*32 + (lane >> 2);
    const int ncl = wn*32 + (lane & 3)*2;
    #pragma unroll
    for (int mt = 0; mt < 2; mt++) {
        #pragma unroll
        for (int nt = 0; nt < 4; nt++) {
            int n = n0 + ncl + nt*8;
            if (n >= N) continue;
            #pragma unroll
            for (int half = 0; half < 2; half++) {
                int m = mrow + mt*16 + half*8;
                float v0 = cf[mt][nt][half*2+0];
                float v1 = cf[mt][nt][half*2+1];
                *(float2*)(Cf + (size_t)m*N + n) = make_float2(v0, v1);
                if (outp)
                    *(float2*)(outp + (size_t)m*(2*DM) + dir*DM + n) = make_float2(v0, v1);
            }
        }
    }
}

// ===========================================================================
// x_proj split-K with FUSED conv+SiLU in the A staging.
// 512 threads, tile 128(M) x 128(N, 80 valid) x 192(K per slice, 3 chunks).
// A staged synchronously (conv from g_xz), B via cp.async double-buffered.
// Also writes f32 xc for the scan (each element staged exactly once).
// ===========================================================================
#define STAGE512 65536
#define SMEM512 (2*STAGE512)

__global__ __launch_bounds__(512, 1)
void k_xproj(const bf16* __restrict__ Whi0, const bf16* __restrict__ Wlo0,
             const bf16* __restrict__ Whi1, const bf16* __restrict__ Wlo1,
             const float* __restrict__ cwF, const float* __restrict__ cwB,
             const float* __restrict__ cbF, const float* __restrict__ cbB,
             float* __restrict__ partial)
{
    extern __shared__ __align__(1024) char smem[];
    const int dir = blockIdx.z;
    const float* xz = g_xz[dir];
    float* xc = g_xc[dir];
    const float* cw = dir ? cwB : cwF;
    const float* cb = dir ? cbB : cbF;
    const bf16* Whi = dir ? Whi1 : Whi0;
    const bf16* Wlo = dir ? Wlo1 : Wlo0;

    const uint32_t tb = smem_u32(smem);
    const int tid = threadIdx.x, lane = tid & 31, wid = tid >> 5;
    const int wm = wid & 3, wn = wid >> 2;
    const int m0 = blockIdx.y * 128;
    const int slice = blockIdx.x;
    const int kbase = slice * XP_KLEN;

    const int l15 = lane & 15;
    const int a_kbx = (lane & 16) ? 16 : 0;
    const int b_nrow = (lane & 7) + ((lane & 16) ? 8 : 0);
    const int b_kbx = (lane & 8) ? 16 : 0;

    uint32_t aOff[2], aMsk[2];
    #pragma unroll
    for (int mt = 0; mt < 2; mt++) {
        int r = wm*32 + mt*16 + l15;
        aOff[mt] = r * 128;
        aMsk[mt] = (r & 7) << 4;
    }
    uint32_t bOff[2], bMsk[2];
    #pragma unroll
    for (int g = 0; g < 2; g++) {
        int r = wn*32 + g*16 + b_nrow;
        bOff[g] = r * 128;
        bMsk[g] = (r & 7) << 4;
    }

    float cf[2][4][4];
    #pragma unroll
    for (int i = 0; i < 2; i++)
        #pragma unroll
        for (int j = 0; j < 4; j++)
            #pragma unroll
            for (int q = 0; q < 4; q++) cf[i][j][q] = 0.f;

    // B stage chunk 0 (cp.async)
    #pragma unroll
    for (int t = 0; t < 2; t++) {
        int idx = tid + t*512;
        int row = idx >> 3, col = idx & 7;
        int kk = kbase + col*8;
        uint32_t soff = (uint32_t)(row*128 + ((col*16) ^ ((row & 7) << 4)));
        int v = (row < DBLW) ? 16 : 0;
        size_t go = (size_t)(v ? row : 0)*DI + kk;
        CP16(tb + 32768 + soff, Whi + go, v);
        CP16(tb + 49152 + soff, Wlo + go, v);
    }
    CP_COMMIT();

    for (int ch = 0; ch < 3; ch++) {
        const int k0 = kbase + ch*GTK;
        char* Abuf = smem + (ch&1)*STAGE512;
        // ---- A staging: conv + SiLU from g_xz (synchronous STS) ----
        #pragma unroll
        for (int t = 0; t < 2; t++) {
            int g = tid + t*512;                 // 128 rows x 8 colgroups
            int row = g >> 3, cg = g & 7;
            int c0 = k0 + cg*8;
            int r = m0 + row;
            int l = r & (LSEQ-1);
            float4 w4[8];
            #pragma unroll
            for (int j = 0; j < 8; j++) w4[j] = *(const float4*)(cw + (size_t)(c0+j)*DC);
            float acc[8];
            {
                float4 b0 = *(const float4*)(cb + c0);
                float4 b1 = *(const float4*)(cb + c0 + 4);
                acc[0]=b0.x; acc[1]=b0.y; acc[2]=b0.z; acc[3]=b0.w;
                acc[4]=b1.x; acc[5]=b1.y; acc[6]=b1.z; acc[7]=b1.w;
            }
            #define XTAP(K_, COMP_) \
                if (l - (DC-1) + (K_) >= 0) { \
                    const float* xr = xz + (size_t)(r - (DC-1) + (K_))*2*DI + c0; \
                    float4 x0 = *(const float4*)xr, x1 = *(const float4*)(xr+4); \
                    acc[0]+=x0.x*w4[0].COMP_; acc[1]+=x0.y*w4[1].COMP_; \
                    acc[2]+=x0.z*w4[2].COMP_; acc[3]+=x0.w*w4[3].COMP_; \
                    acc[4]+=x1.x*w4[4].COMP_; acc[5]+=x1.y*w4[5].COMP_; \
                    acc[6]+=x1.z*w4[6].COMP_; acc[7]+=x1.w*w4[7].COMP_; }
            XTAP(0, x) XTAP(1, y) XTAP(2, z) XTAP(3, w)
            #undef XTAP
            float v[8];
            bf16 vh[8], vl[8];
            #pragma unroll
            for (int j = 0; j < 8; j++) {
                v[j] = acc[j] / (1.f + __expf(-acc[j]));
                fsplit(v[j], &vh[j], &vl[j]);
            }
            // f32 xc out (scan input)
            *(float4*)(xc + (size_t)r*DI + c0)     = make_float4(v[0],v[1],v[2],v[3]);
            *(float4*)(xc + (size_t)r*DI + c0 + 4) = make_float4(v[4],v[5],v[6],v[7]);
            // smem hi/lo (swizzled 16B groups)
            uint32_t soff = (uint32_t)(row*128 + ((cg*16) ^ ((row & 7) << 4)));
            *(uint4*)(Abuf + soff) =
                make_uint4(pk2(vh[0],vh[1]), pk2(vh[2],vh[3]), pk2(vh[4],vh[5]), pk2(vh[6],vh[7]));
            *(uint4*)(Abuf + 16384 + soff) =
                make_uint4(pk2(vl[0],vl[1]), pk2(vl[2],vl[3]), pk2(vl[4],vl[5]), pk2(vl[6],vl[7]));
        }
        // ---- B stage next chunk ----
        if (ch + 1 < 3) {
            uint32_t nb = tb + ((ch+1)&1)*STAGE512;
            int kn = kbase + (ch+1)*GTK;
            #pragma unroll
            for (int t = 0; t < 2; t++) {
                int idx = tid + t*512;
                int row = idx >> 3, col = idx & 7;
                int kk = kn + col*8;
                uint32_t soff = (uint32_t)(row*128 + ((col*16) ^ ((row & 7) << 4)));
                int v = (row < DBLW) ? 16 : 0;
                size_t go = (size_t)(v ? row : 0)*DI + kk;
                CP16(nb + 32768 + soff, Whi + go, v);
                CP16(nb + 49152 + soff, Wlo + go, v);
            }
            CP_COMMIT();
            CP_WAIT1();
        } else {
            CP_WAIT0();
        }
        __syncthreads();

        const uint32_t AHI = tb + (ch&1)*STAGE512;
        const uint32_t ALO = AHI + 16384, BHI = AHI + 32768, BLO = AHI + 49152;
        #pragma unroll
        for (int ks = 0; ks < 4; ks++) {
            const int kb = ks * 32;
            uint32_t ah[2][4], al[2][4], bh[2][4], bl[2][4];
            #pragma unroll
            for (int mt = 0; mt < 2; mt++) {
                uint32_t kx = (uint32_t)(kb + a_kbx) ^ aMsk[mt];
                LDSM4(ah[mt], AHI + aOff[mt] + kx);
                LDSM4(al[mt], ALO + aOff[mt] + kx);
            }
            #pragma unroll
            for (int g = 0; g < 2; g++) {
                uint32_t kx = (uint32_t)(kb + b_kbx) ^ bMsk[g];
                LDSM4(bh[g], BHI + bOff[g] + kx);
                LDSM4(bl[g], BLO + bOff[g] + kx);
            }
            #pragma unroll
            for (int mt = 0; mt < 2; mt++)
                #pragma unroll
                for (int nt = 0; nt < 4; nt++) {
                    int g = nt >> 1, o = (nt & 1) * 2;
                    float* cc = cf[mt][nt];
                    MMA16816(cc, ah[mt], bh[g][o], bh[g][o+1]);
                    MMA16816(cc, ah[mt], bl[g][o], bl[g][o+1]);
                    MMA16816(cc, al[mt], bh[g][o], bh[g][o+1]);
                }
        }
        __syncthreads();
    }

    // partial write
    const int mrow = m0 + wm*32 + (lane >> 2);
    const int ncl = wn*32 + (lane & 3)*2;
    float* pbase = partial + ((size_t)(dir*XP_SLICES + slice))*RWS*128;
    #pragma unroll
    for (int mt = 0; mt < 2; mt++)
        #pragma unroll
        for (int nt = 0; nt < 4; nt++) {
            int n = ncl + nt*8;
            #pragma unroll
            for (int half = 0; half < 2; half++) {
                int m = mrow + mt*16 + half*8;
                *(float2*)(pbase + (size_t)m*128 + n) =
                    make_float2(cf[mt][nt][half*2], cf[mt][nt][half*2+1]);
            }
        }
}

// ===========================================================================
// Delta GEMM with FUSED split-K reduce in the A staging.
// 512 threads, tile 128 x 128, K = 48 (single chunk, zero-padded to 64).
// A = sum of 8 x_proj partials (cols 0:48) -> bf16 hi/lo in smem.
// B = dt_w (cp.async).  Epilogue: +dt_b, softplus -> g_delta.
// ===========================================================================
#define SMEM_DELTA STAGE512

__global__ __launch_bounds__(512, 1)
void k_delta(const bf16* __restrict__ Whi0, const bf16* __restrict__ Wlo0,
             const bf16* __restrict__ Whi1, const bf16* __restrict__ Wlo1,
             const float* __restrict__ b0, const float* __restrict__ b1)
{
    extern __shared__ __align__(1024) char smem[];
    const int dir = blockIdx.z;
    const bf16* Whi = dir ? Whi1 : Whi0;
    const bf16* Wlo = dir ? Wlo1 : Wlo0;
    const float* bias = dir ? b1 : b0;

    const uint32_t tb = smem_u32(smem);
    const int tid = threadIdx.x, lane = tid & 31, wid = tid >> 5;
    const int wm = wid & 3, wn = wid >> 2;
    const int m0 = blockIdx.y * 128;
    const int n0 = blockIdx.x * 128;

    const int l15 = lane & 15;
    const int a_kbx = (lane & 16) ? 16 : 0;
    const int b_nrow = (lane & 7) + ((lane & 16) ? 8 : 0);
    const int b_kbx = (lane & 8) ? 16 : 0;

    uint32_t aOff[2], aMsk[2];
    #pragma unroll
    for (int mt = 0; mt < 2; mt++) {
        int r = wm*32 + mt*16 + l15;
        aOff[mt] = r * 128;
        aMsk[mt] = (r & 7) << 4;
    }
    uint32_t bOff[2], bMsk[2];
    #pragma unroll
    for (int g = 0; g < 2; g++) {
        int r = wn*32 + g*16 + b_nrow;
        bOff[g] = r * 128;
        bMsk[g] = (r & 7) << 4;
    }

    // B stage (single chunk, kk<48 guard)
    #pragma unroll
    for (int t = 0; t < 2; t++) {
        int idx = tid + t*512;
        int row = idx >> 3, col = idx & 7;
        int kk = col*8;
        uint32_t soff = (uint32_t)(row*128 + ((col*16) ^ ((row & 7) << 4)));
        int v = (kk < DTR) ? 16 : 0;
        size_t go = (size_t)(n0+row)*DTR + (v ? kk : 0);
        CP16(tb + 32768 + soff, Whi + go, v);
        CP16(tb + 49152 + soff, Wlo + go, v);
    }
    CP_COMMIT();

    // A stage: reduce 8 partials, cols 0:48 (pad to 64 with zeros)
    #pragma unroll
    for (int t = 0; t < 2; t++) {
        int g = tid + t*512;
        int row = g >> 3, cg = g & 7;
        int c0 = cg*8;
        int r = m0 + row;
        float s[8] = {0,0,0,0,0,0,0,0};
        if (c0 < DTR) {
            const float* p = g_xp_part[dir][0] + (size_t)r*128 + c0;
            #pragma unroll
            for (int sl = 0; sl < XP_SLICES; sl++) {
                float4 q0 = *(const float4*)(p + (size_t)sl*RWS*128);
                float4 q1 = *(const float4*)(p + (size_t)sl*RWS*128 + 4);
                s[0]+=q0.x; s[1]+=q0.y; s[2]+=q0.z; s[3]+=q0.w;
                s[4]+=q1.x; s[5]+=q1.y; s[6]+=q1.z; s[7]+=q1.w;
            }
        }
        bf16 vh[8], vl[8];
        #pragma unroll
        for (int j = 0; j < 8; j++) fsplit(s[j], &vh[j], &vl[j]);
        uint32_t soff = (uint32_t)(row*128 + ((cg*16) ^ ((row & 7) << 4)));
        *(uint4*)(smem + soff) =
            make_uint4(pk2(vh[0],vh[1]), pk2(vh[2],vh[3]), pk2(vh[4],vh[5]), pk2(vh[6],vh[7]));
        *(uint4*)(smem + 16384 + soff) =
            make_uint4(pk2(vl[0],vl[1]), pk2(vl[2],vl[3]), pk2(vl[4],vl[5]), pk2(vl[6],vl[7]));
    }
    CP_WAIT0();
    __syncthreads();

    float cf[2][4][4];
    #pragma unroll
    for (int i = 0; i < 2; i++)
        #pragma unroll
        for (int j = 0; j < 4; j++)
            #pragma unroll
            for (int q = 0; q < 4; q++) cf[i][j][q] = 0.f;

    const uint32_t AHI = tb, ALO = tb + 16384, BHI = tb + 32768, BLO = tb + 49152;
    #pragma unroll
    for (int ks = 0; ks < 4; ks++) {
        const int kb = ks * 32;
        uint32_t ah[2][4], al[2][4], bh[2][4], bl[2][4];
        #pragma unroll
        for (int mt = 0; mt < 2; mt++) {
            uint32_t kx = (uint32_t)(kb + a_kbx) ^ aMsk[mt];
            LDSM4(ah[mt], AHI + aOff[mt] + kx);
            LDSM4(al[mt], ALO + aOff[mt] + kx);
        }
        #pragma unroll
        for (int g = 0; g < 2; g++) {
            uint32_t kx = (uint32_t)(kb + b_kbx) ^ bMsk[g];
            LDSM4(bh[g], BHI + bOff[g] + kx);
            LDSM4(bl[g], BLO + bOff[g] + kx);
        }
        #pragma unroll
        for (int mt = 0; mt < 2; mt++)
            #pragma unroll
            for (int nt = 0; nt < 4; nt++) {
                int g = nt >> 1, o = (nt & 1) * 2;
                float* cc = cf[mt][nt];
                MMA16816(cc, ah[mt], bh[g][o], bh[g][o+1]);
                MMA16816(cc, ah[mt], bl[g][o], bl[g][o+1]);
                MMA16816(cc, al[mt], bh[g][o], bh[g][o+1]);
            }
    }

    float* Cf = g_delta[dir];
    const int mrow = m0 + wm*32 + (lane >> 2);
    const int ncl = wn*32 + (lane & 3)*2;
    #pragma unroll
    for (int mt = 0; mt < 2; mt++) {
        #pragma unroll
        for (int nt = 0; nt < 4; nt++) {
            int n = n0 + ncl + nt*8;
            #pragma unroll
            for (int half = 0; half < 2; half++) {
                int m = mrow + mt*16 + half*8;
                float v0 = cf[mt][nt][half*2+0] + bias[n];
                float v1 = cf[mt][nt][half*2+1] + bias[n+1];
                v0 = (v0 > 20.f) ? v0 : log1pf(__expf(v0));
                v1 = (v1 > 20.f) ? v1 : log1pf(__expf(v1));
                *(float2*)(Cf + (size_t)m*DI + n) = make_float2(v0, v1);
            }
        }
    }
}

// ---------------------------------------------------------------------------
// Selective scan: B/C reduced inline from x_proj partials; ILP fast path.
// ---------------------------------------------------------------------------
#define SCAN_TD 128
#define TCH 64

__global__ __launch_bounds__(SCAN_TD)
void k_scan(const float* __restrict__ alF, const float* __restrict__ alB,
            const float* __restrict__ dpF, const float* __restrict__ dpB) {
    int dir = blockIdx.z;
    int b = blockIdx.y;
    int d = blockIdx.x * SCAN_TD + threadIdx.x;

    const float* Alog = (dir ? alB : alF) + (size_t)d * DS;
    float Arow[DS];
    bool fastA = true;
    #pragma unroll
    for (int n = 0; n < DS; n++) {
        Arow[n] = -__expf(Alog[n]);
        float tgt = -(float)(n+1);
        fastA = fastA && (fabsf(Arow[n] - tgt) <= 1e-4f * (float)(n+1));
    }
    float Dv = (dir ? dpB : dpF)[d];

    float h[DS];
    #pragma unroll
    for (int n = 0; n < DS; n++) h[n] = 0.f;

    __shared__ float sB[TCH][DS];
    __shared__ float sC[TCH][DS];

    const float* delt = g_delta[dir];
    const float* xcb  = g_xc[dir];
    const float* xzb  = g_xz[dir];
    const float* part = g_xp_part[dir][0];
    bf16* yh = g_y_hi[dir];
    bf16* yl = g_y_lo[dir];

    for (int t0 = 0; t0 < LSEQ; t0 += TCH) {
        for (int i = threadIdx.x; i < TCH*DS; i += SCAN_TD) {
            int tt = i / DS, n = i % DS;
            size_t r = (size_t)(b*LSEQ + t0 + tt);
            const float* p = part + r*128;
            float sb = 0.f, sc = 0.f;
            #pragma unroll
            for (int sl = 0; sl < XP_SLICES; sl++) {
                sb += p[(size_t)sl*RWS*128 + DTR + n];
                sc += p[(size_t)sl*RWS*128 + DTR + DS + n];
            }
            sB[tt][n] = sb;
            sC[tt][n] = sc;
        }
        __syncthreads();
        if (fastA) {
            for (int tt = 0; tt < TCH; tt++) {
                size_t r = (size_t)(b*LSEQ + t0 + tt);
                float dv = delt[r*DI + d];
                float xv = xcb[r*DI + d];
                float du = dv * xv;
                float e1 = __expf(-dv);
                float e2 = e1*e1, e4 = e2*e2, e8 = e4*e4;
                float e3 = e2*e1, e5 = e4*e1, e6 = e4*e2, e7 = e4*e3;
                float p[16];
                p[0]=e1;  p[1]=e2;  p[2]=e3;  p[3]=e4;
                p[4]=e5;  p[5]=e6;  p[6]=e7;  p[7]=e8;
                p[8]=e8*e1;  p[9]=e8*e2;  p[10]=e8*e3;  p[11]=e8*e4;
                p[12]=e8*e5; p[13]=e8*e6; p[14]=e8*e7;  p[15]=e8*e8;
                float y0 = 0.f, y1 = 0.f, y2 = 0.f, y3 = 0.f;
                #pragma unroll
                for (int q = 0; q < 4; q++) {
                    float4 b4 = *(const float4*)&sB[tt][q*4];
                    float4 c4 = *(const float4*)&sC[tt][q*4];
                    int n = q*4;
                    h[n+0] = h[n+0]*p[n+0] + du*b4.x;
                    h[n+1] = h[n+1]*p[n+1] + du*b4.y;
                    h[n+2] = h[n+2]*p[n+2] + du*b4.z;
                    h[n+3] = h[n+3]*p[n+3] + du*b4.w;
                    y0 += h[n+0]*c4.x;
                    y1 += h[n+1]*c4.y;
                    y2 += h[n+2]*c4.z;
                    y3 += h[n+3]*c4.w;
                }
                float y = (y0 + y1) + (y2 + y3);
                float zv = xzb[r*2*DI + DI + d];
                float yv = (y + xv*Dv) * (zv / (1.f + __expf(-zv)));
                fsplit(yv, yh + r*DI + d, yl + r*DI + d);
            }
        } else {
            for (int tt = 0; tt < TCH; tt++) {
                size_t r = (size_t)(b*LSEQ + t0 + tt);
                float dv = delt[r*DI + d];
                float xv = xcb[r*DI + d];
                float du = dv * xv;
                float y0 = 0.f, y1 = 0.f, y2 = 0.f, y3 = 0.f;
                #pragma unroll
                for (int q = 0; q < 4; q++) {
                    float4 b4 = *(const float4*)&sB[tt][q*4];
                    float4 c4 = *(const float4*)&sC[tt][q*4];
                    int n = q*4;
                    h[n+0] = h[n+0]*__expf(dv*Arow[n+0]) + du*b4.x;
                    h[n+1] = h[n+1]*__expf(dv*Arow[n+1]) + du*b4.y;
                    h[n+2] = h[n+2]*__expf(dv*Arow[n+2]) + du*b4.z;
                    h[n+3] = h[n+3]*__expf(dv*Arow[n+3]) + du*b4.w;
                    y0 += h[n+0]*c4.x;
                    y1 += h[n+1]*c4.y;
                    y2 += h[n+2]*c4.z;
                    y3 += h[n+3]*c4.w;
                }
                float y = (y0 + y1) + (y2 + y3);
                float zv = xzb[r*2*DI + DI + d];
                float yv = (y + xv*Dv) * (zv / (1.f + __expf(-zv)));
                fsplit(yv, yh + r*DI + d, yl + r*DI + d);
            }
        }
        __syncthreads();
    }
}

// ---------------------------------------------------------------------------
// Host launcher — 6 kernels per layer
// ---------------------------------------------------------------------------
extern "C" void kernel_launch(void* const* d_in, const int* in_sizes, int n_in,
                              void* d_out, int out_size) {
    (void)in_sizes; (void)n_in; (void)out_size;
    const int* ids = (const int*)d_in[0];
    const float* F[11]; const float* Bw[11];
    for (int i = 0; i < 11; i++) {
        F[i]  = (const float*)d_in[1 + i];
        Bw[i] = (const float*)d_in[12 + i];
    }
    float* out = (float*)d_out;

    static int smem_set = 0;
    if (!smem_set) {
        cudaFuncSetAttribute(k_xproj, cudaFuncAttributeMaxDynamicSharedMemorySize, SMEM512);
        cudaFuncSetAttribute(k_delta, cudaFuncAttributeMaxDynamicSharedMemorySize, SMEM_DELTA);
        cudaFuncSetAttribute(k_gemm256, cudaFuncAttributeMaxDynamicSharedMemorySize, SMEM256);
        smem_set = 1;
    }

    bf16 *wip_hi[2], *wip_lo[2], *wxp_hi[2], *wxp_lo[2];
    bf16 *wdt_hi[2], *wdt_lo[2], *wop_hi[2], *wop_lo[2];
    float* xp_part;
    {
        void* p;
        cudaGetSymbolAddress(&p, g_wip_hi); wip_hi[0]=(bf16*)p; wip_hi[1]=(bf16*)p + (size_t)NL*2*DI*DM;
        cudaGetSymbolAddress(&p, g_wip_lo); wip_lo[0]=(bf16*)p; wip_lo[1]=(bf16*)p + (size_t)NL*2*DI*DM;
        cudaGetSymbolAddress(&p, g_wxp_hi); wxp_hi[0]=(bf16*)p; wxp_hi[1]=(bf16*)p + (size_t)NL*DBLW*DI;
        cudaGetSymbolAddress(&p, g_wxp_lo); wxp_lo[0]=(bf16*)p; wxp_lo[1]=(bf16*)p + (size_t)NL*DBLW*DI;
        cudaGetSymbolAddress(&p, g_wdt_hi); wdt_hi[0]=(bf16*)p; wdt_hi[1]=(bf16*)p + (size_t)NL*DI*DTR;
        cudaGetSymbolAddress(&p, g_wdt_lo); wdt_lo[0]=(bf16*)p; wdt_lo[1]=(bf16*)p + (size_t)NL*DI*DTR;
        cudaGetSymbolAddress(&p, g_wop_hi); wop_hi[0]=(bf16*)p; wop_hi[1]=(bf16*)p + (size_t)NL*DM*DI;
        cudaGetSymbolAddress(&p, g_wop_lo); wop_lo[0]=(bf16*)p; wop_lo[1]=(bf16*)p + (size_t)NL*DM*DI;
        cudaGetSymbolAddress(&p, g_xp_part); xp_part = (float*)p;
    }

    {
        int n4 = NL*2*DI*DM/4;
        k_wsplit<<<dim3((n4+255)/256, 2), 256>>>(
            (const float4*)F[2], (const float4*)Bw[2],
            (bf162*)wip_hi[0], (bf162*)wip_lo[0], (bf162*)wip_hi[1], (bf162*)wip_lo[1], n4);
    }
    {
        int n4 = NL*DM*DI/4;
        k_wsplit<<<dim3((n4+255)/256, 2), 256>>>(
            (const float4*)F[10], (const float4*)Bw[10],
            (bf162*)wop_hi[0], (bf162*)wop_lo[0], (bf162*)wop_hi[1], (bf162*)wop_lo[1], n4);
    }
    {
        int n40 = NL*DBLW*DI/4, n41 = NL*DI*DTR/4;
        int gx = ((n40 > n41 ? n40 : n41) + 255)/256;
        k_wsplit2<<<dim3(gx, 4), 256>>>(
            (const float4*)F[5], (const float4*)Bw[5],
            (bf162*)wxp_hi[0], (bf162*)wxp_lo[0], (bf162*)wxp_hi[1], (bf162*)wxp_lo[1], n40,
            (const float4*)F[6], (const float4*)Bw[6],
            (bf162*)wdt_hi[0], (bf162*)wdt_lo[0], (bf162*)wdt_hi[1], (bf162*)wdt_lo[1], n41);
    }
    k_embed<<<dim3(RWS, 2), 192>>>(ids, F[0], Bw[0]);

    for (int layer = 0; layer < NL; layer++) {
        const float* nwF = F[1]  + (size_t)layer*DM;
        const float* nwB = Bw[1] + (size_t)layer*DM;
        const float* cwF = F[3]  + (size_t)layer*DI*DC;
        const float* cwB = Bw[3] + (size_t)layer*DI*DC;
        const float* cbF = F[4]  + (size_t)layer*DI;
        const float* cbB = Bw[4] + (size_t)layer*DI;
        const float* dbF = F[7]  + (size_t)layer*DI;
        const float* dbB = Bw[7] + (size_t)layer*DI;
        const float* alF = F[8]  + (size_t)layer*DI*DS;
        const float* alB = Bw[8] + (size_t)layer*DI*DS;
        const float* dpF = F[9]  + (size_t)layer*DI;
        const float* dpB = Bw[9] + (size_t)layer*DI;

        size_t oip = (size_t)layer*2*DI*DM;
        size_t oxp = (size_t)layer*DBLW*DI;
        size_t odt = (size_t)layer*DI*DTR;
        size_t oop = (size_t)layer*DM*DI;

        k_rmsnorm<<<dim3(RWS, 2), 256>>>(nwF, nwB);

        // in_proj (ncu slot #6 on layer 0)
        k_gemm256<<<dim3(2*DI/64, RWS/128, 2), 256, SMEM256>>>(
            0, DM, wip_hi[0]+oip, wip_lo[0]+oip, wip_hi[1]+oip, wip_lo[1]+oip,
            1, nullptr, RWS, 2*DI, DM);

        // x_proj split-K with fused conv
        k_xproj<<<dim3(XP_SLICES, RWS/128, 2), 512, SMEM512>>>(
            wxp_hi[0]+oxp, wxp_lo[0]+oxp, wxp_hi[1]+oxp, wxp_lo[1]+oxp,
            cwF, cwB, cbF, cbB, xp_part);

        // delta with fused reduce
        k_delta<<<dim3(DI/128, RWS/128, 2), 512, SMEM_DELTA>>>(
            wdt_hi[0]+odt, wdt_lo[0]+odt, wdt_hi[1]+odt, wdt_lo[1]+odt, dbF, dbB);

        // scan with fused B/C reduce
        k_scan<<<dim3(DI/SCAN_TD, BSZ, 2), SCAN_TD>>>(alF, alB, dpF, dpB);

        // out_proj (fused d_out write)
        k_gemm256<<<dim3(DM/64, RWS/128, 2), 256, SMEM256>>>(
            3, DI, wop_hi[0]+oop, wop_lo[0]+oop, wop_hi[1]+oop, wop_lo[1]+oop,
            6, out + (size_t)layer*RWS*2*DM, RWS, DM, DI);
    }
}

// round 17
// speedup vs baseline: 1.1231x; 1.1231x over previous
#include <cuda_runtime.h>
#include <cuda_bf16.h>
#include <cstdint>

#define BSZ 2
#define LSEQ 1024
#define DM 768
#define DI 1536
#define DS 16
#define DC 4
#define DTR 48
#define NL 24
#define RWS (BSZ*LSEQ)
#define DBLW (DTR + 2*DS)       /* 80 */
#define EPSF 1e-5f
#define XP_SLICES 8
#define XP_KLEN (DI/XP_SLICES)  /* 192 */
#define OP_SLICES 2
#define OP_KLEN (DI/OP_SLICES)  /* 768 */

typedef __nv_bfloat16 bf16;
typedef __nv_bfloat162 bf162;

// ---------------------------------------------------------------------------
// Scratch
// ---------------------------------------------------------------------------
__device__ float g_x[2][RWS*DM];
__device__ float g_xz[2][RWS*2*DI];
__device__ float g_xc[2][RWS*DI];
__device__ float g_dbl[2][RWS*DBLW];
__device__ float g_delta[2][RWS*DI];
__device__ float g_xp_part[2][XP_SLICES][RWS*128];
__device__ float g_op_part[2][OP_SLICES][RWS*DM];

__device__ bf16 g_h_hi[2][RWS*DM],   g_h_lo[2][RWS*DM];
__device__ bf16 g_xc_hi[2][RWS*DI],  g_xc_lo[2][RWS*DI];
__device__ bf16 g_dbl_hi[2][RWS*DBLW], g_dbl_lo[2][RWS*DBLW];
__device__ bf16 g_y_hi[2][RWS*DI],   g_y_lo[2][RWS*DI];

__device__ bf16 g_wip_hi[2][NL*2*DI*DM], g_wip_lo[2][NL*2*DI*DM];
__device__ bf16 g_wxp_hi[2][NL*DBLW*DI], g_wxp_lo[2][NL*DBLW*DI];
__device__ bf16 g_wdt_hi[2][NL*DI*DTR],  g_wdt_lo[2][NL*DI*DTR];
__device__ bf16 g_wop_hi[2][NL*DM*DI],   g_wop_lo[2][NL*DM*DI];

__device__ __forceinline__ uint32_t smem_u32(const void* p) {
    uint32_t a;
    asm("{ .reg .u64 t; cvta.to.shared.u64 t, %1; cvt.u32.u64 %0, t; }" : "=r"(a) : "l"(p));
    return a;
}

__device__ __forceinline__ void fsplit(float v, bf16* hp, bf16* lp) {
    bf16 h = __float2bfloat16_rn(v);
    *hp = h;
    *lp = __float2bfloat16_rn(v - __bfloat162float(h));
}

__device__ __forceinline__ const bf16* actA_hi(int aId, int dir) {
    switch (aId) {
        case 0: return g_h_hi[dir];
        case 1: return g_xc_hi[dir];
        case 2: return g_dbl_hi[dir];
        default: return g_y_hi[dir];
    }
}
__device__ __forceinline__ const bf16* actA_lo(int aId, int dir) {
    switch (aId) {
        case 0: return g_h_lo[dir];
        case 1: return g_xc_lo[dir];
        case 2: return g_dbl_lo[dir];
        default: return g_y_lo[dir];
    }
}
__device__ __forceinline__ float* getCf(int cfId, int dir) {
    switch (cfId) {
        case 1: return g_xz[dir];
        case 4: return g_delta[dir];
        default: return g_x[dir];
    }
}

#define CP16(dst, src, sz) \
    asm volatile("cp.async.cg.shared.global [%0], [%1], 16, %2;" \
        :: "r"(dst), "l"(src), "r"(sz) : "memory")
#define CP_COMMIT() asm volatile("cp.async.commit_group;" ::: "memory")
#define CP_WAIT1()  asm volatile("cp.async.wait_group 1;" ::: "memory")
#define CP_WAIT0()  asm volatile("cp.async.wait_group 0;" ::: "memory")

#define LDSM4(r, addr) \
    asm volatile("ldmatrix.sync.aligned.m8n8.x4.shared.b16 {%0,%1,%2,%3}, [%4];" \
        : "=r"((r)[0]), "=r"((r)[1]), "=r"((r)[2]), "=r"((r)[3]) : "r"(addr))

#define MMA16816(c, a, b0v, b1v) \
    asm volatile("mma.sync.aligned.m16n8k16.row.col.f32.bf16.bf16.f32 " \
        "{%0,%1,%2,%3}, {%4,%5,%6,%7}, {%8,%9}, {%0,%1,%2,%3};" \
        : "+f"((c)[0]), "+f"((c)[1]), "+f"((c)[2]), "+f"((c)[3]) \
        : "r"((a)[0]), "r"((a)[1]), "r"((a)[2]), "r"((a)[3]), "r"(b0v), "r"(b1v))

// ---------------------------------------------------------------------------
// Weight split kernels (f32 -> bf16 hi/lo)
// ---------------------------------------------------------------------------
__global__ void k_wsplit(const float4* __restrict__ sF, const float4* __restrict__ sB,
                         bf162* __restrict__ hF, bf162* __restrict__ lF,
                         bf162* __restrict__ hB, bf162* __restrict__ lB, int n4) {
    int i = blockIdx.x * blockDim.x + threadIdx.x;
    if (i >= n4) return;
    const float4* src = blockIdx.y ? sB : sF;
    bf162* hi = blockIdx.y ? hB : hF;
    bf162* lo = blockIdx.y ? lB : lF;
    float4 v = src[i];
    bf162 h01 = __floats2bfloat162_rn(v.x, v.y);
    bf162 h23 = __floats2bfloat162_rn(v.z, v.w);
    bf162 l01 = __floats2bfloat162_rn(v.x - __bfloat162float(h01.x),
                                      v.y - __bfloat162float(h01.y));
    bf162 l23 = __floats2bfloat162_rn(v.z - __bfloat162float(h23.x),
                                      v.w - __bfloat162float(h23.y));
    hi[i*2] = h01; hi[i*2+1] = h23;
    lo[i*2] = l01; lo[i*2+1] = l23;
}

__global__ void k_wsplit2(const float4* __restrict__ s0F, const float4* __restrict__ s0B,
                          bf162* __restrict__ h0F, bf162* __restrict__ l0F,
                          bf162* __restrict__ h0B, bf162* __restrict__ l0B, int n40,
                          const float4* __restrict__ s1F, const float4* __restrict__ s1B,
                          bf162* __restrict__ h1F, bf162* __restrict__ l1F,
                          bf162* __restrict__ h1B, bf162* __restrict__ l1B, int n41) {
    int i = blockIdx.x * blockDim.x + threadIdx.x;
    int set = blockIdx.y >> 1, dir = blockIdx.y & 1;
    const float4* src; bf162 *hi, *lo; int n4;
    if (set == 0) { src = dir ? s0B : s0F; hi = dir ? h0B : h0F; lo = dir ? l0B : l0F; n4 = n40; }
    else          { src = dir ? s1B : s1F; hi = dir ? h1B : h1F; lo = dir ? l1B : l1F; n4 = n41; }
    if (i >= n4) return;
    float4 v = src[i];
    bf162 h01 = __floats2bfloat162_rn(v.x, v.y);
    bf162 h23 = __floats2bfloat162_rn(v.z, v.w);
    bf162 l01 = __floats2bfloat162_rn(v.x - __bfloat162float(h01.x),
                                      v.y - __bfloat162float(h01.y));
    bf162 l23 = __floats2bfloat162_rn(v.z - __bfloat162float(h23.x),
                                      v.w - __bfloat162float(h23.y));
    hi[i*2] = h01; hi[i*2+1] = h23;
    lo[i*2] = l01; lo[i*2+1] = l23;
}

// ---------------------------------------------------------------------------
// Embedding
// ---------------------------------------------------------------------------
__global__ void k_embed(const int* __restrict__ ids,
                        const float* __restrict__ embF,
                        const float* __restrict__ embB) {
    int row = blockIdx.x, dir = blockIdx.y;
    int b = row / LSEQ, l = row % LSEQ;
    int tok = (dir == 0) ? ids[b*LSEQ + l] : ids[b*LSEQ + (LSEQ-1-l)];
    const float* emb = (dir == 0) ? embF : embB;
    const float4* src = (const float4*)(emb + (size_t)tok * DM);
    float4* dst = (float4*)(g_x[dir] + (size_t)row * DM);
    for (int i = threadIdx.x; i < DM/4; i += blockDim.x) dst[i] = src[i];
}

// ---------------------------------------------------------------------------
// RMSNorm -> bf16 hi/lo
// ---------------------------------------------------------------------------
__global__ void k_rmsnorm(const float* __restrict__ wF, const float* __restrict__ wB) {
    int row = blockIdx.x, dir = blockIdx.y;
    const float* x = g_x[dir] + (size_t)row * DM;
    bf16* hh = g_h_hi[dir] + (size_t)row * DM;
    bf16* hl = g_h_lo[dir] + (size_t)row * DM;
    const float* w = dir ? wB : wF;
    float s = 0.f;
    for (int i = threadIdx.x; i < DM; i += 256) { float v = x[i]; s += v*v; }
    #pragma unroll
    for (int o = 16; o; o >>= 1) s += __shfl_down_sync(0xffffffffu, s, o);
    __shared__ float red[8];
    if ((threadIdx.x & 31) == 0) red[threadIdx.x >> 5] = s;
    __syncthreads();
    if (threadIdx.x < 8) {
        float t = red[threadIdx.x];
        #pragma unroll
        for (int o = 4; o; o >>= 1) t += __shfl_down_sync(0xffu, t, o);
        if (threadIdx.x == 0) red[0] = t;
    }
    __syncthreads();
    float inv = rsqrtf(red[0] / (float)DM + EPSF);
    for (int i = threadIdx.x; i < DM; i += 256) {
        float v = x[i] * inv * w[i];
        fsplit(v, hh + i, hl + i);
    }
}

// ===========================================================================
// KERNEL A: 128x128 tile, 512 threads, 1 CTA/SM (x_proj split-K, delta)
// ===========================================================================
#define GTK 64
#define STAGE512 65536
#define SMEM512 (2*STAGE512)

__device__ __forceinline__ void stage512(
    uint32_t stg,
    const bf16* __restrict__ Ahi, const bf16* __restrict__ Alo,
    const bf16* __restrict__ Whi, const bf16* __restrict__ Wlo,
    int m0, int n0, int k0, int lda, int ldw, int N, int K, int tid)
{
    #pragma unroll
    for (int t = 0; t < 2; t++) {
        int idx = tid + t*512;
        int row = idx >> 3, col = idx & 7;
        int kk = k0 + col*8;
        uint32_t soff = (uint32_t)(row*128 + ((col*16) ^ ((row & 7) << 4)));
        int asz = (kk < K) ? 16 : 0;
        size_t aoffm = (size_t)(m0+row)*lda + (asz ? kk : 0);
        CP16(stg + soff,          Ahi + aoffm, asz);
        CP16(stg + 16384 + soff,  Alo + aoffm, asz);
        int gn = n0 + row;
        int bsz = (gn < N && kk < K) ? 16 : 0;
        size_t boff = (size_t)(bsz ? gn : 0)*ldw + (bsz ? kk : 0);
        CP16(stg + 32768 + soff,  Whi + boff, bsz);
        CP16(stg + 49152 + soff,  Wlo + boff, bsz);
    }
}

__global__ __launch_bounds__(512, 1)
void k_gemm512(int aId, int lda,
               const bf16* __restrict__ Whi0, const bf16* __restrict__ Wlo0,
               const bf16* __restrict__ Whi1, const bf16* __restrict__ Wlo1,
               int cfId, int M, int N, int K,
               const float* __restrict__ b0, const float* __restrict__ b1,
               int epi, int splitK, float* __restrict__ partial)
{
    extern __shared__ __align__(1024) char smem[];
    const int dir = blockIdx.z;
    const bf16* Ahi = actA_hi(aId, dir);
    const bf16* Alo = actA_lo(aId, dir);
    const bf16* Whi = dir ? Whi1 : Whi0;
    const bf16* Wlo = dir ? Wlo1 : Wlo0;
    const float* bias = dir ? b1 : b0;

    const uint32_t tb = smem_u32(smem);
    const int tid = threadIdx.x, lane = tid & 31, wid = tid >> 5;
    const int wm = wid & 3, wn = wid >> 2;
    const int m0 = blockIdx.y * 128;
    int n0, kbase, kLen, slice = 0;
    if (splitK) { slice = blockIdx.x; n0 = 0; kLen = XP_KLEN; kbase = slice * XP_KLEN; }
    else        { n0 = blockIdx.x * 128; kLen = K; kbase = 0; }

    const int l15 = lane & 15;
    const int a_kbx = (lane & 16) ? 16 : 0;
    const int b_nrow = (lane & 7) + ((lane & 16) ? 8 : 0);
    const int b_kbx = (lane & 8) ? 16 : 0;

    uint32_t aOff[2], aMsk[2];
    #pragma unroll
    for (int mt = 0; mt < 2; mt++) {
        int r = wm*32 + mt*16 + l15;
        aOff[mt] = r * 128;
        aMsk[mt] = (r & 7) << 4;
    }
    uint32_t bOff[2], bMsk[2];
    #pragma unroll
    for (int g = 0; g < 2; g++) {
        int r = wn*32 + g*16 + b_nrow;
        bOff[g] = r * 128;
        bMsk[g] = (r & 7) << 4;
    }

    float cf[2][4][4];
    #pragma unroll
    for (int i = 0; i < 2; i++)
        #pragma unroll
        for (int j = 0; j < 4; j++)
            #pragma unroll
            for (int q = 0; q < 4; q++) cf[i][j][q] = 0.f;

    const int nch = (kLen + GTK - 1) / GTK;
    stage512(tb, Ahi, Alo, Whi, Wlo, m0, n0, kbase, lda, K, N, K, tid);
    CP_COMMIT();

    for (int ch = 0; ch < nch; ch++) {
        if (ch + 1 < nch) {
            stage512(tb + ((ch+1)&1)*STAGE512, Ahi, Alo, Whi, Wlo,
                     m0, n0, kbase + (ch+1)*GTK, lda, K, N, K, tid);
            CP_COMMIT();
            CP_WAIT1();
        } else {
            CP_WAIT0();
        }
        __syncthreads();

        const uint32_t AHI = tb + (ch&1)*STAGE512;
        const uint32_t ALO = AHI + 16384, BHI = AHI + 32768, BLO = AHI + 49152;
        #pragma unroll
        for (int ks = 0; ks < 4; ks++) {
            const int kb = ks * 32;
            uint32_t ah[2][4], al[2][4], bh[2][4], bl[2][4];
            #pragma unroll
            for (int mt = 0; mt < 2; mt++) {
                uint32_t kx = (uint32_t)(kb + a_kbx) ^ aMsk[mt];
                LDSM4(ah[mt], AHI + aOff[mt] + kx);
                LDSM4(al[mt], ALO + aOff[mt] + kx);
            }
            #pragma unroll
            for (int g = 0; g < 2; g++) {
                uint32_t kx = (uint32_t)(kb + b_kbx) ^ bMsk[g];
                LDSM4(bh[g], BHI + bOff[g] + kx);
                LDSM4(bl[g], BLO + bOff[g] + kx);
            }
            #pragma unroll
            for (int mt = 0; mt < 2; mt++)
                #pragma unroll
                for (int nt = 0; nt < 4; nt++) {
                    int g = nt >> 1, o = (nt & 1) * 2;
                    float* cc = cf[mt][nt];
                    MMA16816(cc, ah[mt], bh[g][o], bh[g][o+1]);
                    MMA16816(cc, ah[mt], bl[g][o], bl[g][o+1]);
                    MMA16816(cc, al[mt], bh[g][o], bh[g][o+1]);
                }
        }
        __syncthreads();
    }

    const int mrow = m0 + wm*32 + (lane >> 2);
    const int ncl = wn*32 + (lane & 3)*2;
    if (splitK) {
        float* pbase = partial + ((size_t)(dir*XP_SLICES + slice))*RWS*128;
        #pragma unroll
        for (int mt = 0; mt < 2; mt++)
            #pragma unroll
            for (int nt = 0; nt < 4; nt++) {
                int n = ncl + nt*8;
                #pragma unroll
                for (int half = 0; half < 2; half++) {
                    int m = mrow + mt*16 + half*8;
                    *(float2*)(pbase + (size_t)m*128 + n) =
                        make_float2(cf[mt][nt][half*2], cf[mt][nt][half*2+1]);
                }
            }
        return;
    }
    float* Cf = getCf(cfId, dir);
    #pragma unroll
    for (int mt = 0; mt < 2; mt++) {
        #pragma unroll
        for (int nt = 0; nt < 4; nt++) {
            int n = n0 + ncl + nt*8;
            if (n >= N) continue;
            #pragma unroll
            for (int half = 0; half < 2; half++) {
                int m = mrow + mt*16 + half*8;
                float v0 = cf[mt][nt][half*2+0];
                float v1 = cf[mt][nt][half*2+1];
                if (epi == 1) {
                    v0 += bias[n];   v1 += bias[n+1];
                    v0 = (v0 > 20.f) ? v0 : log1pf(__expf(v0));
                    v1 = (v1 > 20.f) ? v1 : log1pf(__expf(v1));
                }
                *(float2*)(Cf + (size_t)m*N + n) = make_float2(v0, v1);
            }
        }
    }
}

// ===========================================================================
// KERNEL B: 128x64 tile, 256 threads, 2 CTAs/SM (in_proj, out_proj)
// Optional split-K partial mode for out_proj.
// ===========================================================================
#define STAGE256 49152
#define SMEM256 (2*STAGE256)

__device__ __forceinline__ void stage256(
    uint32_t stg,
    const bf16* __restrict__ Ahi, const bf16* __restrict__ Alo,
    const bf16* __restrict__ Whi, const bf16* __restrict__ Wlo,
    int m0, int n0, int k0, int lda, int ldw, int N, int K, int tid)
{
    #pragma unroll
    for (int t = 0; t < 4; t++) {
        int idx = tid + t*256;
        int row = idx >> 3, col = idx & 7;
        int kk = k0 + col*8;
        uint32_t soff = (uint32_t)(row*128 + ((col*16) ^ ((row & 7) << 4)));
        int v = (kk < K) ? 16 : 0;
        size_t go = (size_t)(m0+row)*lda + (v ? kk : 0);
        CP16(stg + soff,         Ahi + go, v);
        CP16(stg + 16384 + soff, Alo + go, v);
    }
    #pragma unroll
    for (int t = 0; t < 2; t++) {
        int idx = tid + t*256;
        int row = idx >> 3, col = idx & 7;
        int kk = k0 + col*8;
        uint32_t soff = (uint32_t)(row*128 + ((col*16) ^ ((row & 7) << 4)));
        int gn = n0 + row;
        int v = (gn < N && kk < K) ? 16 : 0;
        size_t go = (size_t)(v ? gn : 0)*ldw + (v ? kk : 0);
        CP16(stg + 32768 + soff, Whi + go, v);
        CP16(stg + 40960 + soff, Wlo + go, v);
    }
}

__global__ __launch_bounds__(256, 2)
void k_gemm256(int aId, int lda,
               const bf16* __restrict__ Whi0, const bf16* __restrict__ Wlo0,
               const bf16* __restrict__ Whi1, const bf16* __restrict__ Wlo1,
               int cfId, float* __restrict__ outp, int M, int N, int K,
               int nsl, int kSlice, float* __restrict__ partial)
{
    extern __shared__ __align__(1024) char smem[];
    const int dir = blockIdx.z;
    const bf16* Ahi = actA_hi(aId, dir);
    const bf16* Alo = actA_lo(aId, dir);
    const bf16* Whi = dir ? Whi1 : Whi0;
    const bf16* Wlo = dir ? Wlo1 : Wlo0;

    const uint32_t tb = smem_u32(smem);
    const int tid = threadIdx.x, lane = tid & 31, wid = tid >> 5;
    const int wm = wid & 3, wn = wid >> 2;
    const int m0 = blockIdx.y * 128;
    int n0, kbase, kLen, slice = 0;
    if (nsl > 1) {
        int ntN = N >> 6;                 // N multiple of 64
        slice = blockIdx.x / ntN;
        n0 = (blockIdx.x - slice * ntN) * 64;
        kbase = slice * kSlice;
        kLen = kSlice;
    } else {
        n0 = blockIdx.x * 64; kbase = 0; kLen = K;
    }

    const int l15 = lane & 15;
    const int a_kbx = (lane & 16) ? 16 : 0;
    const int b_nrow = (lane & 7) + ((lane & 16) ? 8 : 0);
    const int b_kbx = (lane & 8) ? 16 : 0;

    uint32_t aOff[2], aMsk[2];
    #pragma unroll
    for (int mt = 0; mt < 2; mt++) {
        int r = wm*32 + mt*16 + l15;
        aOff[mt] = r * 128;
        aMsk[mt] = (r & 7) << 4;
    }
    uint32_t bOff[2], bMsk[2];
    #pragma unroll
    for (int g = 0; g < 2; g++) {
        int r = wn*32 + g*16 + b_nrow;
        bOff[g] = r * 128;
        bMsk[g] = (r & 7) << 4;
    }

    float cf[2][4][4];
    #pragma unroll
    for (int i = 0; i < 2; i++)
        #pragma unroll
        for (int j = 0; j < 4; j++)
            #pragma unroll
            for (int q = 0; q < 4; q++) cf[i][j][q] = 0.f;

    const int nch = (kLen + GTK - 1) / GTK;
    stage256(tb, Ahi, Alo, Whi, Wlo, m0, n0, kbase, lda, K, N, K, tid);
    CP_COMMIT();

    for (int ch = 0; ch < nch; ch++) {
        if (ch + 1 < nch) {
            stage256(tb + ((ch+1)&1)*STAGE256, Ahi, Alo, Whi, Wlo,
                     m0, n0, kbase + (ch+1)*GTK, lda, K, N, K, tid);
            CP_COMMIT();
            CP_WAIT1();
        } else {
            CP_WAIT0();
        }
        __syncthreads();

        const uint32_t AHI = tb + (ch&1)*STAGE256;
        const uint32_t ALO = AHI + 16384, BHI = AHI + 32768, BLO = AHI + 40960;
        #pragma unroll
        for (int ks = 0; ks < 4; ks++) {
            const int kb = ks * 32;
            uint32_t ah[2][4], al[2][4], bh[2][4], bl[2][4];
            #pragma unroll
            for (int mt = 0; mt < 2; mt++) {
                uint32_t kx = (uint32_t)(kb + a_kbx) ^ aMsk[mt];
                LDSM4(ah[mt], AHI + aOff[mt] + kx);
                LDSM4(al[mt], ALO + aOff[mt] + kx);
            }
            #pragma unroll
            for (int g = 0; g < 2; g++) {
                uint32_t kx = (uint32_t)(kb + b_kbx) ^ bMsk[g];
                LDSM4(bh[g], BHI + bOff[g] + kx);
                LDSM4(bl[g], BLO + bOff[g] + kx);
            }
            #pragma unroll
            for (int mt = 0; mt < 2; mt++)
                #pragma unroll
                for (int nt = 0; nt < 4; nt++) {
                    int g = nt >> 1, o = (nt & 1) * 2;
                    float* cc = cf[mt][nt];
                    MMA16816(cc, ah[mt], bh[g][o], bh[g][o+1]);
                    MMA16816(cc, ah[mt], bl[g][o], bl[g][o+1]);
                    MMA16816(cc, al[mt], bh[g][o], bh[g][o+1]);
                }
        }
        __syncthreads();
    }

    const int mrow = m0 + wm*32 + (lane >> 2);
    const int ncl = wn*32 + (lane & 3)*2;
    if (nsl > 1) {
        float* pbase = partial + ((size_t)(dir*nsl + slice)) * (size_t)M * N;
        #pragma unroll
        for (int mt = 0; mt < 2; mt++)
            #pragma unroll
            for (int nt = 0; nt < 4; nt++) {
                int n = n0 + ncl + nt*8;
                #pragma unroll
                for (int half = 0; half < 2; half++) {
                    int m = mrow + mt*16 + half*8;
                    *(float2*)(pbase + (size_t)m*N + n) =
                        make_float2(cf[mt][nt][half*2], cf[mt][nt][half*2+1]);
                }
            }
        return;
    }
    float* Cf = getCf(cfId, dir);
    #pragma unroll
    for (int mt = 0; mt < 2; mt++) {
        #pragma unroll
        for (int nt = 0; nt < 4; nt++) {
            int n = n0 + ncl + nt*8;
            if (n >= N) continue;
            #pragma unroll
            for (int half = 0; half < 2; half++) {
                int m = mrow + mt*16 + half*8;
                float v0 = cf[mt][nt][half*2+0];
                float v1 = cf[mt][nt][half*2+1];
                *(float2*)(Cf + (size_t)m*N + n) = make_float2(v0, v1);
                if (outp)
                    *(float2*)(outp + (size_t)m*(2*DM) + dir*DM + n) = make_float2(v0, v1);
            }
        }
    }
}

// ---------------------------------------------------------------------------
// out_proj split-K reduce -> g_x + d_out slice
// ---------------------------------------------------------------------------
__global__ __launch_bounds__(256)
void k_op_reduce(float* __restrict__ outp) {
    int idx = blockIdx.x * 256 + threadIdx.x;   // over RWS*DM/4
    int dir = blockIdx.y;
    if (idx >= RWS*DM/4) return;
    float4 a = ((const float4*)g_op_part[dir][0])[idx];
    float4 b = ((const float4*)g_op_part[dir][1])[idx];
    float4 v = make_float4(a.x+b.x, a.y+b.y, a.z+b.z, a.w+b.w);
    ((float4*)g_x[dir])[idx] = v;
    int m = idx / (DM/4), c4 = idx % (DM/4);
    *(float4*)(outp + (size_t)m*(2*DM) + dir*DM + c4*4) = v;
}

// ---------------------------------------------------------------------------
// x_proj split-K reduce -> g_dbl f32 + bf16 hi/lo
// ---------------------------------------------------------------------------
__global__ void k_xp_reduce() {
    int idx = blockIdx.x * blockDim.x + threadIdx.x;
    int dir = blockIdx.y;
    if (idx >= RWS*DBLW) return;
    int m = idx / DBLW, n = idx % DBLW;
    const float* p = g_xp_part[dir][0] + (size_t)m*128 + n;
    float s = 0.f;
    #pragma unroll
    for (int sl = 0; sl < XP_SLICES; sl++) s += p[(size_t)sl*RWS*128];
    g_dbl[dir][idx] = s;
    fsplit(s, &g_dbl_hi[dir][idx], &g_dbl_lo[dir][idx]);
}

// ---------------------------------------------------------------------------
// Conv1d (k=4) + bias + SiLU -> f32 + bf16 hi/lo
// ---------------------------------------------------------------------------
__global__ void k_conv(const float* __restrict__ cwF, const float* __restrict__ cwB,
                       const float* __restrict__ cbF, const float* __restrict__ cbB) {
    int idx = blockIdx.x * blockDim.x + threadIdx.x;
    int dir = blockIdx.y;
    if (idx >= RWS*DI) return;
    int row = idx / DI, c = idx % DI;
    int b = row / LSEQ, l = row % LSEQ;
    const float* cw = (dir ? cwB : cwF) + c*DC;
    float acc = (dir ? cbB : cbF)[c];
    const float* xz = g_xz[dir];
    #pragma unroll
    for (int k = 0; k < DC; k++) {
        int ls = l - (DC-1) + k;
        if (ls >= 0) acc += xz[((size_t)(b*LSEQ + ls))*2*DI + c] * cw[k];
    }
    float v = acc / (1.f + __expf(-acc));
    g_xc[dir][idx] = v;
    fsplit(v, &g_xc_hi[dir][idx], &g_xc_lo[dir][idx]);
}

// ---------------------------------------------------------------------------
// Selective scan + D-skip + silu(z) gating -> bf16 hi/lo y  (ILP fast path)
// ---------------------------------------------------------------------------
#define SCAN_TD 128
#define TCH 64

__global__ __launch_bounds__(SCAN_TD)
void k_scan(const float* __restrict__ alF, const float* __restrict__ alB,
            const float* __restrict__ dpF, const float* __restrict__ dpB) {
    int dir = blockIdx.z;
    int b = blockIdx.y;
    int d = blockIdx.x * SCAN_TD + threadIdx.x;

    const float* Alog = (dir ? alB : alF) + (size_t)d * DS;
    float Arow[DS];
    bool fastA = true;
    #pragma unroll
    for (int n = 0; n < DS; n++) {
        Arow[n] = -__expf(Alog[n]);
        float tgt = -(float)(n+1);
        fastA = fastA && (fabsf(Arow[n] - tgt) <= 1e-4f * (float)(n+1));
    }
    float Dv = (dir ? dpB : dpF)[d];

    float h[DS];
    #pragma unroll
    for (int n = 0; n < DS; n++) h[n] = 0.f;

    __shared__ float sB[TCH][DS];
    __shared__ float sC[TCH][DS];

    const float* dbl  = g_dbl[dir];
    const float* delt = g_delta[dir];
    const float* xcb  = g_xc[dir];
    const float* xzb  = g_xz[dir];
    bf16* yh = g_y_hi[dir];
    bf16* yl = g_y_lo[dir];

    for (int t0 = 0; t0 < LSEQ; t0 += TCH) {
        for (int i = threadIdx.x; i < TCH*DS; i += SCAN_TD) {
            int tt = i / DS, n = i % DS;
            size_t r = (size_t)(b*LSEQ + t0 + tt);
            sB[tt][n] = dbl[r*DBLW + DTR + n];
            sC[tt][n] = dbl[r*DBLW + DTR + DS + n];
        }
        __syncthreads();
        if (fastA) {
            for (int tt = 0; tt < TCH; tt++) {
                size_t r = (size_t)(b*LSEQ + t0 + tt);
                float dv = delt[r*DI + d];
                float xv = xcb[r*DI + d];
                float du = dv * xv;
                float e1 = __expf(-dv);
                float e2 = e1*e1, e4 = e2*e2, e8 = e4*e4;
                float e3 = e2*e1, e5 = e4*e1, e6 = e4*e2, e7 = e4*e3;
                float p[16];
                p[0]=e1;  p[1]=e2;  p[2]=e3;  p[3]=e4;
                p[4]=e5;  p[5]=e6;  p[6]=e7;  p[7]=e8;
                p[8]=e8*e1;  p[9]=e8*e2;  p[10]=e8*e3;  p[11]=e8*e4;
                p[12]=e8*e5; p[13]=e8*e6; p[14]=e8*e7;  p[15]=e8*e8;
                float y0 = 0.f, y1 = 0.f, y2 = 0.f, y3 = 0.f;
                #pragma unroll
                for (int q = 0; q < 4; q++) {
                    float4 b4 = *(const float4*)&sB[tt][q*4];
                    float4 c4 = *(const float4*)&sC[tt][q*4];
                    int n = q*4;
                    h[n+0] = h[n+0]*p[n+0] + du*b4.x;
                    h[n+1] = h[n+1]*p[n+1] + du*b4.y;
                    h[n+2] = h[n+2]*p[n+2] + du*b4.z;
                    h[n+3] = h[n+3]*p[n+3] + du*b4.w;
                    y0 += h[n+0]*c4.x;
                    y1 += h[n+1]*c4.y;
                    y2 += h[n+2]*c4.z;
                    y3 += h[n+3]*c4.w;
                }
                float y = (y0 + y1) + (y2 + y3);
                float zv = xzb[r*2*DI + DI + d];
                float yv = (y + xv*Dv) * (zv / (1.f + __expf(-zv)));
                fsplit(yv, yh + r*DI + d, yl + r*DI + d);
            }
        } else {
            for (int tt = 0; tt < TCH; tt++) {
                size_t r = (size_t)(b*LSEQ + t0 + tt);
                float dv = delt[r*DI + d];
                float xv = xcb[r*DI + d];
                float du = dv * xv;
                float y0 = 0.f, y1 = 0.f, y2 = 0.f, y3 = 0.f;
                #pragma unroll
                for (int q = 0; q < 4; q++) {
                    float4 b4 = *(const float4*)&sB[tt][q*4];
                    float4 c4 = *(const float4*)&sC[tt][q*4];
                    int n = q*4;
                    h[n+0] = h[n+0]*__expf(dv*Arow[n+0]) + du*b4.x;
                    h[n+1] = h[n+1]*__expf(dv*Arow[n+1]) + du*b4.y;
                    h[n+2] = h[n+2]*__expf(dv*Arow[n+2]) + du*b4.z;
                    h[n+3] = h[n+3]*__expf(dv*Arow[n+3]) + du*b4.w;
                    y0 += h[n+0]*c4.x;
                    y1 += h[n+1]*c4.y;
                    y2 += h[n+2]*c4.z;
                    y3 += h[n+3]*c4.w;
                }
                float y = (y0 + y1) + (y2 + y3);
                float zv = xzb[r*2*DI + DI + d];
                float yv = (y + xv*Dv) * (zv / (1.f + __expf(-zv)));
                fsplit(yv, yh + r*DI + d, yl + r*DI + d);
            }
        }
        __syncthreads();
    }
}

// ---------------------------------------------------------------------------
// Host launcher (R14 structure, no probe, out_proj split-K=2)
// ---------------------------------------------------------------------------
extern "C" void kernel_launch(void* const* d_in, const int* in_sizes, int n_in,
                              void* d_out, int out_size) {
    (void)in_sizes; (void)n_in; (void)out_size;
    const int* ids = (const int*)d_in[0];
    const float* F[11]; const float* Bw[11];
    for (int i = 0; i < 11; i++) {
        F[i]  = (const float*)d_in[1 + i];
        Bw[i] = (const float*)d_in[12 + i];
    }
    float* out = (float*)d_out;

    static int smem_set = 0;
    if (!smem_set) {
        cudaFuncSetAttribute(k_gemm512, cudaFuncAttributeMaxDynamicSharedMemorySize, SMEM512);
        cudaFuncSetAttribute(k_gemm256, cudaFuncAttributeMaxDynamicSharedMemorySize, SMEM256);
        smem_set = 1;
    }

    bf16 *wip_hi[2], *wip_lo[2], *wxp_hi[2], *wxp_lo[2];
    bf16 *wdt_hi[2], *wdt_lo[2], *wop_hi[2], *wop_lo[2];
    float *xp_part, *op_part;
    {
        void* p;
        cudaGetSymbolAddress(&p, g_wip_hi); wip_hi[0]=(bf16*)p; wip_hi[1]=(bf16*)p + (size_t)NL*2*DI*DM;
        cudaGetSymbolAddress(&p, g_wip_lo); wip_lo[0]=(bf16*)p; wip_lo[1]=(bf16*)p + (size_t)NL*2*DI*DM;
        cudaGetSymbolAddress(&p, g_wxp_hi); wxp_hi[0]=(bf16*)p; wxp_hi[1]=(bf16*)p + (size_t)NL*DBLW*DI;
        cudaGetSymbolAddress(&p, g_wxp_lo); wxp_lo[0]=(bf16*)p; wxp_lo[1]=(bf16*)p + (size_t)NL*DBLW*DI;
        cudaGetSymbolAddress(&p, g_wdt_hi); wdt_hi[0]=(bf16*)p; wdt_hi[1]=(bf16*)p + (size_t)NL*DI*DTR;
        cudaGetSymbolAddress(&p, g_wdt_lo); wdt_lo[0]=(bf16*)p; wdt_lo[1]=(bf16*)p + (size_t)NL*DI*DTR;
        cudaGetSymbolAddress(&p, g_wop_hi); wop_hi[0]=(bf16*)p; wop_hi[1]=(bf16*)p + (size_t)NL*DM*DI;
        cudaGetSymbolAddress(&p, g_wop_lo); wop_lo[0]=(bf16*)p; wop_lo[1]=(bf16*)p + (size_t)NL*DM*DI;
        cudaGetSymbolAddress(&p, g_xp_part); xp_part = (float*)p;
        cudaGetSymbolAddress(&p, g_op_part); op_part = (float*)p;
    }

    {
        int n4 = NL*2*DI*DM/4;
        k_wsplit<<<dim3((n4+255)/256, 2), 256>>>(
            (const float4*)F[2], (const float4*)Bw[2],
            (bf162*)wip_hi[0], (bf162*)wip_lo[0], (bf162*)wip_hi[1], (bf162*)wip_lo[1], n4);
    }
    {
        int n4 = NL*DM*DI/4;
        k_wsplit<<<dim3((n4+255)/256, 2), 256>>>(
            (const float4*)F[10], (const float4*)Bw[10],
            (bf162*)wop_hi[0], (bf162*)wop_lo[0], (bf162*)wop_hi[1], (bf162*)wop_lo[1], n4);
    }
    {
        int n40 = NL*DBLW*DI/4, n41 = NL*DI*DTR/4;
        int gx = ((n40 > n41 ? n40 : n41) + 255)/256;
        k_wsplit2<<<dim3(gx, 4), 256>>>(
            (const float4*)F[5], (const float4*)Bw[5],
            (bf162*)wxp_hi[0], (bf162*)wxp_lo[0], (bf162*)wxp_hi[1], (bf162*)wxp_lo[1], n40,
            (const float4*)F[6], (const float4*)Bw[6],
            (bf162*)wdt_hi[0], (bf162*)wdt_lo[0], (bf162*)wdt_hi[1], (bf162*)wdt_lo[1], n41);
    }
    k_embed<<<dim3(RWS, 2), 192>>>(ids, F[0], Bw[0]);

    for (int layer = 0; layer < NL; layer++) {
        const float* nwF = F[1]  + (size_t)layer*DM;
        const float* nwB = Bw[1] + (size_t)layer*DM;
        const float* cwF = F[3]  + (size_t)layer*DI*DC;
        const float* cwB = Bw[3] + (size_t)layer*DI*DC;
        const float* cbF = F[4]  + (size_t)layer*DI;
        const float* cbB = Bw[4] + (size_t)layer*DI;
        const float* dbF = F[7]  + (size_t)layer*DI;
        const float* dbB = Bw[7] + (size_t)layer*DI;
        const float* alF = F[8]  + (size_t)layer*DI*DS;
        const float* alB = Bw[8] + (size_t)layer*DI*DS;
        const float* dpF = F[9]  + (size_t)layer*DI;
        const float* dpB = Bw[9] + (size_t)layer*DI;

        size_t oip = (size_t)layer*2*DI*DM;
        size_t oxp = (size_t)layer*DBLW*DI;
        size_t odt = (size_t)layer*DI*DTR;
        size_t oop = (size_t)layer*DM*DI;

        k_rmsnorm<<<dim3(RWS, 2), 256>>>(nwF, nwB);

        // in_proj
        k_gemm256<<<dim3(2*DI/64, RWS/128, 2), 256, SMEM256>>>(
            0, DM, wip_hi[0]+oip, wip_lo[0]+oip, wip_hi[1]+oip, wip_lo[1]+oip,
            1, nullptr, RWS, 2*DI, DM, 1, 0, nullptr);

        // conv + split
        k_conv<<<dim3(RWS*DI/256, 2), 256>>>(cwF, cwB, cbF, cbB);

        // x_proj split-K=8
        k_gemm512<<<dim3(XP_SLICES, RWS/128, 2), 512, SMEM512>>>(
            1, DI, wxp_hi[0]+oxp, wxp_lo[0]+oxp, wxp_hi[1]+oxp, wxp_lo[1]+oxp,
            0, RWS, DBLW, DI, nullptr, nullptr, 0, 1, xp_part);
        k_xp_reduce<<<dim3((RWS*DBLW+255)/256, 2), 256>>>();

        // delta (softplus epi)
        k_gemm512<<<dim3(DI/128, RWS/128, 2), 512, SMEM512>>>(
            2, DBLW, wdt_hi[0]+odt, wdt_lo[0]+odt, wdt_hi[1]+odt, wdt_lo[1]+odt,
            4, RWS, DI, DTR, dbF, dbB, 1, 0, nullptr);

        // scan
        k_scan<<<dim3(DI/SCAN_TD, BSZ, 2), SCAN_TD>>>(alF, alB, dpF, dpB);

        // out_proj split-K=2 -> partials, then reduce + d_out write
        k_gemm256<<<dim3(OP_SLICES*(DM/64), RWS/128, 2), 256, SMEM256>>>(
            3, DI, wop_hi[0]+oop, wop_lo[0]+oop, wop_hi[1]+oop, wop_lo[1]+oop,
            6, nullptr, RWS, DM, DI, OP_SLICES, OP_KLEN, op_part);
        k_op_reduce<<<dim3((RWS*DM/4+255)/256, 2), 256>>>(out + (size_t)layer*RWS*2*DM);
    }
}